// round 4
// baseline (speedup 1.0000x reference)
#include <cuda_runtime.h>
#include <cuda_fp16.h>
#include <cuda_bf16.h>

// Synapse_66400194396810: out[m,n] = tanh( w2 . tanh( w1 @ (A[m,n], pre[n], post[m]) + b1 ) + b2 )
// M = N = 4096, Nh = 8.
// R4: inner tanh via tanh.approx.f16x2 (2 tanh / MUFU op): MUFU 576 -> 320 cyc/warp;
//     z + accumulation stay fp32 (FFMA) for accuracy; FMA pipe (~400 cyc) now binding.

#define NH 8

// Layout: [0..23] w1 (row-major [8][3]), [24..31] b1, [32..39] w2, [40] b2
__constant__ float CW[48];

__device__ __forceinline__ float htanh(float x) {
    float y;
    asm("tanh.approx.f32 %0, %1;" : "=f"(y) : "f"(x));
    return y;
}
__device__ __forceinline__ __half2 htanh2(__half2 x) {
    __half2 y;
    asm("tanh.approx.f16x2 %0, %1;" : "=r"(*(unsigned*)&y) : "r"(*(unsigned*)&x));
    return y;
}

// Writes the __constant__ backing store via its global-space alias.
__global__ void pack_weights(const float* __restrict__ w1, const float* __restrict__ b1,
                             const float* __restrict__ w2, const float* __restrict__ b2,
                             float* __restrict__ cw) {
    const int i = threadIdx.x;
    if (i < 24)      cw[i] = w1[i];
    else if (i < 32) cw[i] = b1[i - 24];
    else if (i < 40) cw[i] = w2[i - 32];
    else if (i == 40) cw[i] = b2[0];
}

__global__ void __launch_bounds__(256) synapse_kernel(
    const float* __restrict__ A,
    const float* __restrict__ pre,
    const float* __restrict__ post,
    float* __restrict__ out,
    int Ncols)
{
    const int m = blockIdx.y;
    const int n = (blockIdx.x * blockDim.x + threadIdx.x) * 8;
    if (n >= Ncols) return;
    const int base = m * Ncols + n;

    const float pm = post[m];
    const float4 a0 = *reinterpret_cast<const float4*>(A + base);
    const float4 a1 = *reinterpret_cast<const float4*>(A + base + 4);
    const float4 p0 = *reinterpret_cast<const float4*>(pre + n);
    const float4 p1 = *reinterpret_cast<const float4*>(pre + n + 4);

    // Row-constant part: c[h] = w1[h][2]*post[m] + b1[h]
    float c[NH];
#pragma unroll
    for (int h = 0; h < NH; h++) c[h] = fmaf(CW[h * 3 + 2], pm, CW[24 + h]);

    const float av[8] = {a0.x, a0.y, a0.z, a0.w, a1.x, a1.y, a1.z, a1.w};
    const float pv[8] = {p0.x, p0.y, p0.z, p0.w, p1.x, p1.y, p1.z, p1.w};
    float o[8];
#pragma unroll
    for (int j = 0; j < 8; j++) {
        // Layer-1 preactivations in fp32 (exact).
        float z[NH];
#pragma unroll
        for (int h = 0; h < NH; h++)
            z[h] = fmaf(CW[h * 3], av[j], fmaf(CW[h * 3 + 1], pv[j], c[h]));

        // Inner tanh: pack h-pairs, one f16x2 MUFU op per pair.
        float acc = CW[40];
#pragma unroll
        for (int hp = 0; hp < NH / 2; hp++) {
            __half2 zp = __floats2half2_rn(z[2 * hp], z[2 * hp + 1]);  // F2FP
            __half2 tp = htanh2(zp);
            float2 tf = __half22float2(tp);                             // 2x F2F
            acc = fmaf(CW[32 + 2 * hp],     tf.x, acc);
            acc = fmaf(CW[32 + 2 * hp + 1], tf.y, acc);
        }
        o[j] = htanh(acc);  // final tanh in fp32 (accurate, cheap)
    }
    *reinterpret_cast<float4*>(out + base)     = make_float4(o[0], o[1], o[2], o[3]);
    *reinterpret_cast<float4*>(out + base + 4) = make_float4(o[4], o[5], o[6], o[7]);
}

extern "C" void kernel_launch(void* const* d_in, const int* in_sizes, int n_in,
                              void* d_out, int out_size) {
    const float* A    = (const float*)d_in[0];
    const float* pre  = (const float*)d_in[1];
    const float* post = (const float*)d_in[2];
    const float* w1   = (const float*)d_in[3];
    const float* b1   = (const float*)d_in[4];
    const float* w2   = (const float*)d_in[5];
    const float* b2   = (const float*)d_in[6];
    float* out = (float*)d_out;

    void* cw_alias = nullptr;
    cudaGetSymbolAddress(&cw_alias, CW);

    pack_weights<<<1, 64>>>(w1, b1, w2, b2, (float*)cw_alias);

    const int Ncols = in_sizes[1];        // 4096
    const int M     = out_size / Ncols;   // 4096

    dim3 block(256);
    dim3 grid((Ncols / 8 + 255) / 256, M);  // (2, 4096)
    synapse_kernel<<<grid, block>>>(A, pre, post, out, Ncols);
}

// round 5
// speedup vs baseline: 1.1388x; 1.1388x over previous
#include <cuda_runtime.h>
#include <cuda_fp16.h>
#include <cuda_bf16.h>

// Synapse_66400194396810: out[m,n] = tanh( w2 . tanh( w1 @ (A[m,n], pre[n], post[m]) + b1 ) + b2 )
// M = N = 4096, Nh = 8.
// R5: element-paired all-half2 pipeline. Weights pre-converted to half2 broadcasts in
//     pack_weights (zero hot-path weight cvt). Per 8 elems: only ~17 cvt ops (R4 had 96,
//     which shared the SFU/cvt path with MUFU and regressed). MUFU 40 instr/warp-8elem
//     (320 cyc) binding. Final tanh fp32 for accuracy.

#define NH 8

// Half2-broadcast weight banks (each unsigned = one half value duplicated in both lanes).
// [0..7]=w10, [8..15]=w11, [16..23]=w12, [24..31]=b1, [32..39]=w2, [40]=b2
__constant__ unsigned CWH[48];

__device__ __forceinline__ float htanh(float x) {
    float y;
    asm("tanh.approx.f32 %0, %1;" : "=f"(y) : "f"(x));
    return y;
}
__device__ __forceinline__ __half2 htanh2(__half2 x) {
    unsigned yi;
    asm("tanh.approx.f16x2 %0, %1;" : "=r"(yi) : "r"(*(unsigned*)&x));
    return *(__half2*)&yi;
}
__device__ __forceinline__ __half2 cwh2(int i) {
    unsigned v = CWH[i];
    return *(__half2*)&v;
}

// One-time weight conversion: fp32 -> half2 broadcast, written through the
// __constant__ bank's global alias. Ordered before the main kernel by the launch boundary.
__global__ void pack_weights(const float* __restrict__ w1, const float* __restrict__ b1,
                             const float* __restrict__ w2, const float* __restrict__ b2,
                             unsigned* __restrict__ cwh) {
    const int i = threadIdx.x;
    if (i < NH) {
        __half2 h;
        h = __half2half2(__float2half_rn(w1[i * 3 + 0])); cwh[i]      = *(unsigned*)&h;
        h = __half2half2(__float2half_rn(w1[i * 3 + 1])); cwh[8 + i]  = *(unsigned*)&h;
        h = __half2half2(__float2half_rn(w1[i * 3 + 2])); cwh[16 + i] = *(unsigned*)&h;
        h = __half2half2(__float2half_rn(b1[i]));         cwh[24 + i] = *(unsigned*)&h;
        h = __half2half2(__float2half_rn(w2[i]));         cwh[32 + i] = *(unsigned*)&h;
        if (i == 0) {
            h = __half2half2(__float2half_rn(b2[0]));     cwh[40]     = *(unsigned*)&h;
        }
    }
}

__global__ void __launch_bounds__(256) synapse_kernel(
    const float* __restrict__ A,
    const float* __restrict__ pre,
    const float* __restrict__ post,
    float* __restrict__ out,
    int Ncols)
{
    const int m = blockIdx.y;
    const int n = (blockIdx.x * blockDim.x + threadIdx.x) * 8;
    if (n >= Ncols) return;
    const int base = m * Ncols + n;

    const __half2 pm2 = __float2half2_rn(post[m]);
    const float4 a0 = *reinterpret_cast<const float4*>(A + base);
    const float4 a1 = *reinterpret_cast<const float4*>(A + base + 4);
    const float4 p0 = *reinterpret_cast<const float4*>(pre + n);
    const float4 p1 = *reinterpret_cast<const float4*>(pre + n + 4);

    // Row-constant part: ch[h] = w12[h]*post[m] + b1[h], in half2 broadcast.
    __half2 ch[NH];
#pragma unroll
    for (int h = 0; h < NH; h++) ch[h] = __hfma2(cwh2(16 + h), pm2, cwh2(24 + h));

    const float av[8] = {a0.x, a0.y, a0.z, a0.w, a1.x, a1.y, a1.z, a1.w};
    const float pv[8] = {p0.x, p0.y, p0.z, p0.w, p1.x, p1.y, p1.z, p1.w};
    float o[8];
#pragma unroll
    for (int i = 0; i < 4; i++) {                         // element pairs (2i, 2i+1)
        const __half2 a2 = __floats2half2_rn(av[2 * i], av[2 * i + 1]);
        const __half2 p2 = __floats2half2_rn(pv[2 * i], pv[2 * i + 1]);
        __half2 acc2 = cwh2(40);
#pragma unroll
        for (int h = 0; h < NH; h++) {
            __half2 z2 = __hfma2(cwh2(h), a2, __hfma2(cwh2(8 + h), p2, ch[h]));
            acc2 = __hfma2(cwh2(32 + h), htanh2(z2), acc2);
        }
        const float2 f2 = __half22float2(acc2);
        o[2 * i]     = htanh(f2.x);                        // final tanh in fp32
        o[2 * i + 1] = htanh(f2.y);
    }
    *reinterpret_cast<float4*>(out + base)     = make_float4(o[0], o[1], o[2], o[3]);
    *reinterpret_cast<float4*>(out + base + 4) = make_float4(o[4], o[5], o[6], o[7]);
}

extern "C" void kernel_launch(void* const* d_in, const int* in_sizes, int n_in,
                              void* d_out, int out_size) {
    const float* A    = (const float*)d_in[0];
    const float* pre  = (const float*)d_in[1];
    const float* post = (const float*)d_in[2];
    const float* w1   = (const float*)d_in[3];
    const float* b1   = (const float*)d_in[4];
    const float* w2   = (const float*)d_in[5];
    const float* b2   = (const float*)d_in[6];
    float* out = (float*)d_out;

    void* cwh_alias = nullptr;
    cudaGetSymbolAddress(&cwh_alias, CWH);

    pack_weights<<<1, 32>>>(w1, b1, w2, b2, (unsigned*)cwh_alias);

    const int Ncols = in_sizes[1];        // 4096
    const int M     = out_size / Ncols;   // 4096

    dim3 block(256);
    dim3 grid((Ncols / 8 + 255) / 256, M);  // (2, 4096)
    synapse_kernel<<<grid, block>>>(A, pre, post, out, Ncols);
}

// round 6
// speedup vs baseline: 1.1473x; 1.0074x over previous
#include <cuda_runtime.h>
#include <cuda_fp16.h>
#include <cuda_bf16.h>

// Synapse_66400194396810: out[m,n] = tanh( w2 . tanh( w1 @ (A[m,n], pre[n], post[m]) + b1 ) + b2 )
// M = N = 4096, Nh = 8.
// R6: latency-bound diagnosis (R3 fp32 and R5 half2 both ~40us despite 1.8x MUFU delta;
//     occ was the mover). Keep half2 math; shrink to 4 elems/thread + launch_bounds(256,6)
//     to force regs<=42 -> 6 blocks/SM = 75% occ. Floors: DRAM ~17us, MUFU ~18us.

#define NH 8

// Half2-broadcast weight banks: [0..7]=w10, [8..15]=w11, [16..23]=w12, [24..31]=b1, [32..39]=w2, [40]=b2
__constant__ unsigned CWH[48];

__device__ __forceinline__ float htanh(float x) {
    float y;
    asm("tanh.approx.f32 %0, %1;" : "=f"(y) : "f"(x));
    return y;
}
__device__ __forceinline__ __half2 htanh2(__half2 x) {
    unsigned yi;
    asm("tanh.approx.f16x2 %0, %1;" : "=r"(yi) : "r"(*(unsigned*)&x));
    return *(__half2*)&yi;
}
__device__ __forceinline__ __half2 cwh2(int i) {
    unsigned v = CWH[i];
    return *(__half2*)&v;
}

// One-time fp32 -> half2-broadcast weight conversion, via the constant bank's global alias.
__global__ void pack_weights(const float* __restrict__ w1, const float* __restrict__ b1,
                             const float* __restrict__ w2, const float* __restrict__ b2,
                             unsigned* __restrict__ cwh) {
    const int i = threadIdx.x;
    if (i < NH) {
        __half2 h;
        h = __half2half2(__float2half_rn(w1[i * 3 + 0])); cwh[i]      = *(unsigned*)&h;
        h = __half2half2(__float2half_rn(w1[i * 3 + 1])); cwh[8 + i]  = *(unsigned*)&h;
        h = __half2half2(__float2half_rn(w1[i * 3 + 2])); cwh[16 + i] = *(unsigned*)&h;
        h = __half2half2(__float2half_rn(b1[i]));         cwh[24 + i] = *(unsigned*)&h;
        h = __half2half2(__float2half_rn(w2[i]));         cwh[32 + i] = *(unsigned*)&h;
        if (i == 0) {
            h = __half2half2(__float2half_rn(b2[0]));     cwh[40]     = *(unsigned*)&h;
        }
    }
}

__global__ void __launch_bounds__(256, 6) synapse_kernel(
    const float* __restrict__ A,
    const float* __restrict__ pre,
    const float* __restrict__ post,
    float* __restrict__ out,
    int Ncols)
{
    const int m = blockIdx.y;
    const int n = (blockIdx.x * blockDim.x + threadIdx.x) * 4;
    if (n >= Ncols) return;
    const int base = m * Ncols + n;

    // Issue both global loads immediately (max MLP), then convert; fp32 temps die early.
    const float4 a4 = *reinterpret_cast<const float4*>(A + base);
    const float4 p4 = *reinterpret_cast<const float4*>(pre + n);
    const __half2 pm2 = __float2half2_rn(post[m]);

    const __half2 a2lo = __floats2half2_rn(a4.x, a4.y);
    const __half2 a2hi = __floats2half2_rn(a4.z, a4.w);
    const __half2 p2lo = __floats2half2_rn(p4.x, p4.y);
    const __half2 p2hi = __floats2half2_rn(p4.z, p4.w);

    // Row-constant part: ch[h] = w12[h]*post[m] + b1[h] (half2 broadcast).
    __half2 ch[NH];
#pragma unroll
    for (int h = 0; h < NH; h++) ch[h] = __hfma2(cwh2(16 + h), pm2, cwh2(24 + h));

    __half2 acc_lo = cwh2(40);
    __half2 acc_hi = cwh2(40);
#pragma unroll
    for (int h = 0; h < NH; h++) {
        const __half2 w0 = cwh2(h), w1h = cwh2(8 + h), w2h = cwh2(32 + h);
        __half2 zlo = __hfma2(w0, a2lo, __hfma2(w1h, p2lo, ch[h]));
        __half2 zhi = __hfma2(w0, a2hi, __hfma2(w1h, p2hi, ch[h]));
        acc_lo = __hfma2(w2h, htanh2(zlo), acc_lo);
        acc_hi = __hfma2(w2h, htanh2(zhi), acc_hi);
    }

    const float2 flo = __half22float2(acc_lo);
    const float2 fhi = __half22float2(acc_hi);
    float4 r;
    r.x = htanh(flo.x);  // final tanh in fp32 (accuracy headroom)
    r.y = htanh(flo.y);
    r.z = htanh(fhi.x);
    r.w = htanh(fhi.y);
    *reinterpret_cast<float4*>(out + base) = r;
}

extern "C" void kernel_launch(void* const* d_in, const int* in_sizes, int n_in,
                              void* d_out, int out_size) {
    const float* A    = (const float*)d_in[0];
    const float* pre  = (const float*)d_in[1];
    const float* post = (const float*)d_in[2];
    const float* w1   = (const float*)d_in[3];
    const float* b1   = (const float*)d_in[4];
    const float* w2   = (const float*)d_in[5];
    const float* b2   = (const float*)d_in[6];
    float* out = (float*)d_out;

    void* cwh_alias = nullptr;
    cudaGetSymbolAddress(&cwh_alias, CWH);

    pack_weights<<<1, 32>>>(w1, b1, w2, b2, (unsigned*)cwh_alias);

    const int Ncols = in_sizes[1];        // 4096
    const int M     = out_size / Ncols;   // 4096

    dim3 block(256);
    dim3 grid((Ncols / 4 + 255) / 256, M);  // (4, 4096)
    synapse_kernel<<<grid, block>>>(A, pre, post, out, Ncols);
}